// round 8
// baseline (speedup 1.0000x reference)
#include <cuda_runtime.h>
#include <cuda_bf16.h>
#include <cstdint>

#define NN 100000
#define NE 1600000
#define FF 128
#define CC 64
#define SCAN_B 1024
#define SCAN_NB ((NN + SCAN_B - 1) / SCAN_B)   // 98

// pipeline chunking (node ranges)
#define C0N 50048
#define C0B 391
#define C1N (NN - C0N)          // 49952
#define C1B ((C1N + 127) / 128) // 391

// ======================= scratch (static device globals) =======================
__device__ int   g_cnt[NN];
__device__ int   g_rowptr[NN + 1];
__device__ int   g_cursor[NN];
__device__ int   g_blksum[SCAN_NB];
__device__ int   g_col[NE];
__device__ uint32_t g_xbf[(size_t)NN * 64];    // x as packed bf16x2 (gather source)
__device__ uint32_t g_pbf[(size_t)NN * 32];    // P = h@W2l^T as packed bf16x2 (64 cols)
__device__ float g_q[(size_t)NN * 64];         // Q = h@W2r^T + b2l (fp32)
__device__ float g_xr[(size_t)NN * 128];       // x @ W1r^T (computed on side stream)
__device__ uint32_t g_mhi[(size_t)NN * 64];    // mean(x) packed bf16x2 hi
__device__ uint32_t g_mlo[(size_t)NN * 64];    // mean(x) packed bf16x2 lo
__device__ uint32_t g_hhi[(size_t)NN * 64];    // h packed bf16x2 hi
__device__ uint32_t g_hlo[(size_t)NN * 64];    // h packed bf16x2 lo
// weights as bf16 hi/lo, row-major [n][k]
__device__ unsigned short g_w1hi[128 * 256];
__device__ unsigned short g_w1lo[128 * 256];
__device__ unsigned short g_w2hi[128 * 128];
__device__ unsigned short g_w2lo[128 * 128];

// ======================= small helpers =======================
__device__ __forceinline__ uint32_t smem_to_u32(const void* p) {
    uint32_t a;
    asm("{ .reg .u64 t; cvta.to.shared.u64 t, %1; cvt.u32.u64 %0, t; }" : "=r"(a) : "l"(p));
    return a;
}

__device__ __forceinline__ void ldm_x4(uint32_t* r, uint32_t addr) {
    asm volatile("ldmatrix.sync.aligned.m8n8.x4.shared.b16 {%0,%1,%2,%3}, [%4];"
                 : "=r"(r[0]), "=r"(r[1]), "=r"(r[2]), "=r"(r[3]) : "r"(addr));
}

__device__ __forceinline__ void mma_bf16(float* d, const uint32_t* a, uint32_t b0, uint32_t b1) {
    asm volatile(
        "mma.sync.aligned.m16n8k16.row.col.f32.bf16.bf16.f32 "
        "{%0,%1,%2,%3}, {%4,%5,%6,%7}, {%8,%9}, {%0,%1,%2,%3};"
        : "+f"(d[0]), "+f"(d[1]), "+f"(d[2]), "+f"(d[3])
        : "r"(a[0]), "r"(a[1]), "r"(a[2]), "r"(a[3]), "r"(b0), "r"(b1));
}

__device__ __forceinline__ void split_pack(float a, float b, uint32_t& hi, uint32_t& lo) {
    __nv_bfloat16 ah = __float2bfloat16(a), bh = __float2bfloat16(b);
    float ar = a - __bfloat162float(ah);
    float br = b - __bfloat162float(bh);
    hi = (uint32_t)__bfloat16_as_ushort(ah) | ((uint32_t)__bfloat16_as_ushort(bh) << 16);
    lo = (uint32_t)__bfloat16_as_ushort(__float2bfloat16(ar))
       | ((uint32_t)__bfloat16_as_ushort(__float2bfloat16(br)) << 16);
}

__device__ __forceinline__ uint32_t pack_bf16x2(float a, float b) {
    return (uint32_t)__bfloat16_as_ushort(__float2bfloat16(a))
         | ((uint32_t)__bfloat16_as_ushort(__float2bfloat16(b)) << 16);
}

// ======================= CSR build =======================
__global__ void k_count(const int* __restrict__ dst) {
    int e = blockIdx.x * blockDim.x + threadIdx.x;
    if (e < NE) atomicAdd(&g_cnt[dst[e]], 1);
}

__global__ void k_scan1() {
    __shared__ int sh[SCAN_B];
    int t = threadIdx.x;
    int i = blockIdx.x * SCAN_B + t;
    int v = (i < NN) ? g_cnt[i] : 0;
    if (i < NN) g_cnt[i] = 0;     // re-zero for next replay
    sh[t] = v;
    __syncthreads();
#pragma unroll
    for (int off = 1; off < SCAN_B; off <<= 1) {
        int u = (t >= off) ? sh[t - off] : 0;
        __syncthreads();
        sh[t] += u;
        __syncthreads();
    }
    if (i < NN) g_rowptr[i] = sh[t] - v;
    if (t == SCAN_B - 1) g_blksum[blockIdx.x] = sh[t];
}

__global__ void k_scan2() {
    __shared__ int sh[128];
    int t = threadIdx.x;
    int v = (t < SCAN_NB) ? g_blksum[t] : 0;
    sh[t] = v;
    __syncthreads();
#pragma unroll
    for (int off = 1; off < 128; off <<= 1) {
        int u = (t >= off) ? sh[t - off] : 0;
        __syncthreads();
        sh[t] += u;
        __syncthreads();
    }
    if (t < SCAN_NB) g_blksum[t] = sh[t] - v;
}

__global__ void k_scan3() {
    int i = blockIdx.x * SCAN_B + threadIdx.x;
    if (i < NN) {
        int r = g_rowptr[i] + g_blksum[blockIdx.x];
        g_rowptr[i] = r;
        g_cursor[i] = r;
    }
    if (i == 0) g_rowptr[NN] = NE;
}

__global__ void k_fill(const int* __restrict__ src, const int* __restrict__ dst) {
    int e = blockIdx.x * blockDim.x + threadIdx.x;
    if (e < NE) {
        int d = dst[e];
        int pos = atomicAdd(&g_cursor[d], 1);
        g_col[pos] = src[e];
    }
}

// ======================= x -> packed bf16 (gather source) =======================
__global__ void k_xconv(const float* __restrict__ X) {
    int i = blockIdx.x * blockDim.x + threadIdx.x;   // one u32 output each
    if (i < NN * 64) {
        float2 v = *(const float2*)(X + (size_t)i * 2);
        g_xbf[i] = pack_bf16x2(v.x, v.y);
    }
}

// ======================= aggregation (warp per node, bf16 gather) =======================
__global__ void k_agg128(int nodeBase, int nodeCount) {
    int n = blockIdx.x * (blockDim.x >> 5) + (threadIdx.x >> 5);
    if (n >= nodeCount) return;
    int node = nodeBase + n;
    int lane = threadIdx.x & 31;
    int b = g_rowptr[node], e = g_rowptr[node + 1];
    float a0 = 0.f, a1 = 0.f, a2 = 0.f, a3 = 0.f;
    int i = b;
    for (; i + 4 <= e; i += 4) {
        int u0 = g_col[i + 0], u1 = g_col[i + 1], u2 = g_col[i + 2], u3 = g_col[i + 3];
        uint2 w0 = *((const uint2*)(g_xbf + (size_t)u0 * 64) + lane);
        uint2 w1 = *((const uint2*)(g_xbf + (size_t)u1 * 64) + lane);
        uint2 w2 = *((const uint2*)(g_xbf + (size_t)u2 * 64) + lane);
        uint2 w3 = *((const uint2*)(g_xbf + (size_t)u3 * 64) + lane);
        a0 += __uint_as_float(w0.x << 16) + __uint_as_float(w1.x << 16)
            + __uint_as_float(w2.x << 16) + __uint_as_float(w3.x << 16);
        a1 += __uint_as_float(w0.x & 0xffff0000u) + __uint_as_float(w1.x & 0xffff0000u)
            + __uint_as_float(w2.x & 0xffff0000u) + __uint_as_float(w3.x & 0xffff0000u);
        a2 += __uint_as_float(w0.y << 16) + __uint_as_float(w1.y << 16)
            + __uint_as_float(w2.y << 16) + __uint_as_float(w3.y << 16);
        a3 += __uint_as_float(w0.y & 0xffff0000u) + __uint_as_float(w1.y & 0xffff0000u)
            + __uint_as_float(w2.y & 0xffff0000u) + __uint_as_float(w3.y & 0xffff0000u);
    }
    for (; i < e; i++) {
        uint2 w = *((const uint2*)(g_xbf + (size_t)g_col[i] * 64) + lane);
        a0 += __uint_as_float(w.x << 16);
        a1 += __uint_as_float(w.x & 0xffff0000u);
        a2 += __uint_as_float(w.y << 16);
        a3 += __uint_as_float(w.y & 0xffff0000u);
    }
    float inv = 1.f / (float)max(e - b, 1);
    uint32_t h0, l0, h1, l1;
    split_pack(a0 * inv, a1 * inv, h0, l0);
    split_pack(a2 * inv, a3 * inv, h1, l1);
    *((uint2*)(g_mhi + (size_t)node * 64) + lane) = make_uint2(h0, h1);
    *((uint2*)(g_mlo + (size_t)node * 64) + lane) = make_uint2(l0, l1);
}

// ======================= weight prep =======================
__global__ void k_prepW(const float* __restrict__ W1l, const float* __restrict__ W1r,
                        const float* __restrict__ W2l, const float* __restrict__ W2r) {
    int idx = blockIdx.x * blockDim.x + threadIdx.x;
    if (idx < 128 * 256) {
        int n = idx >> 8, k = idx & 255;
        float w = (k < 128) ? W1l[n * 128 + k] : W1r[n * 128 + (k - 128)];
        __nv_bfloat16 h = __float2bfloat16(w);
        g_w1hi[idx] = __bfloat16_as_ushort(h);
        g_w1lo[idx] = __bfloat16_as_ushort(__float2bfloat16(w - __bfloat162float(h)));
    } else {
        int i2 = idx - 128 * 256;
        if (i2 < 128 * 128) {
            int n = i2 >> 7, k = i2 & 127;
            float w = (n < 64) ? W2l[n * 128 + k] : W2r[(n - 64) * 128 + k];
            __nv_bfloat16 h = __float2bfloat16(w);
            g_w2hi[i2] = __bfloat16_as_ushort(h);
            g_w2lo[i2] = __bfloat16_as_ushort(__float2bfloat16(w - __bfloat162float(h)));
        }
    }
}

// ======================= HMMA GEMM (all K=128) =======================
// LAYER 0: xr = x @ W1r^T                   -> g_xr fp32   (side stream, full range)
// LAYER 1: h  = relu(mean @ W1l^T + xr +b1) -> g_hhi/g_hlo (chunked)
// LAYER 2: P|Q = h @ [W2l;W2r]^T (+b2 hi)   -> g_pbf bf16 / g_q fp32 (chunked)
#define ASTR 72
#define BSTR 136

template <int LAYER>
__global__ void __launch_bounds__(256, 2)
k_mmagemm(const float* __restrict__ X, const float* __restrict__ b1,
          const float* __restrict__ b2, int moff)
{
    constexpr int AHI   = 0;
    constexpr int ALO   = 128 * ASTR * 2;
    constexpr int BHI   = 2 * 128 * ASTR * 2;
    constexpr int BSPL  = 128 * BSTR * 2;
    constexpr int BLO   = BHI + BSPL;

    extern __shared__ char smem[];
    const uint32_t smem_base = smem_to_u32(smem);
    const int tid  = threadIdx.x;
    const int warp = tid >> 5;
    const int lane = tid & 31;
    const int wr   = warp >> 2;
    const int wc   = warp & 3;
    const int mbase = moff + blockIdx.x * 128;

    {
        const uint4* shi;
        const uint4* slo;
        int srowv, woff8;
        if (LAYER <= 1) {
            shi = (const uint4*)g_w1hi; slo = (const uint4*)g_w1lo;
            srowv = 32; woff8 = (LAYER == 0) ? 16 : 0;
        } else {
            shi = (const uint4*)g_w2hi; slo = (const uint4*)g_w2lo;
            srowv = 16; woff8 = 0;
        }
        for (int i = tid; i < 128 * 16; i += 256) {
            int n = i >> 4, c = i & 15;
            *(uint4*)(smem + BHI + n * (BSTR * 2) + c * 16) = shi[n * srowv + woff8 + c];
            *(uint4*)(smem + BLO + n * (BSTR * 2) + c * 16) = slo[n * srowv + woff8 + c];
        }
    }

    float acc[4][4][4];
#pragma unroll
    for (int mt = 0; mt < 4; mt++)
#pragma unroll
        for (int nt = 0; nt < 4; nt++)
#pragma unroll
            for (int q = 0; q < 4; q++) acc[mt][nt][q] = 0.f;

    const uint32_t a_lane_off = (uint32_t)(((lane & 15) * ASTR + (lane >> 4) * 8) * 2);
    const uint32_t* Bh = (const uint32_t*)(smem + BHI);
    const uint32_t* Bl = (const uint32_t*)(smem + BLO);

#pragma unroll
    for (int ch = 0; ch < 2; ch++) {
        __syncthreads();
        {
            int row  = tid >> 1;
            int half = tid & 1;
            int gr   = mbase + row;
            bool valid = gr < NN;
            uint32_t* dAh = (uint32_t*)(smem + AHI + row * (ASTR * 2));
            uint32_t* dAl = (uint32_t*)(smem + ALO + row * (ASTR * 2));
            if (LAYER == 0) {
                const float* src = X + (size_t)gr * 128 + ch * 64 + half * 32;
#pragma unroll
                for (int j = 0; j < 8; j++) {
                    float4 v = make_float4(0.f, 0.f, 0.f, 0.f);
                    if (valid) v = *(const float4*)(src + j * 4);
                    uint32_t h0, l0, h1, l1;
                    split_pack(v.x, v.y, h0, l0);
                    split_pack(v.z, v.w, h1, l1);
                    int o = half * 16 + j * 2;
                    dAh[o] = h0; dAh[o + 1] = h1;
                    dAl[o] = l0; dAl[o + 1] = l1;
                }
            } else {
                const uint32_t* shi = (LAYER == 1) ? g_mhi : g_hhi;
                const uint32_t* slo = (LAYER == 1) ? g_mlo : g_hlo;
                size_t off = (size_t)gr * 64 + ch * 32 + half * 16;
#pragma unroll
                for (int j = 0; j < 4; j++) {
                    uint4 vh = make_uint4(0u, 0u, 0u, 0u), vl = vh;
                    if (valid) {
                        vh = *(const uint4*)(shi + off + j * 4);
                        vl = *(const uint4*)(slo + off + j * 4);
                    }
                    *(uint4*)(dAh + half * 16 + j * 4) = vh;
                    *(uint4*)(dAl + half * 16 + j * 4) = vl;
                }
            }
        }
        __syncthreads();

#pragma unroll
        for (int ks = 0; ks < 4; ks++) {
            const int k0 = ks * 16;
            uint32_t bh[4][2], bl[4][2];
#pragma unroll
            for (int nt = 0; nt < 4; nt++) {
                int n = wc * 32 + nt * 8 + (lane >> 2);
                int bi = n * (BSTR / 2) + (ch * 64 + k0) / 2 + (lane & 3);
                bh[nt][0] = Bh[bi];     bh[nt][1] = Bh[bi + 4];
                bl[nt][0] = Bl[bi];     bl[nt][1] = Bl[bi + 4];
            }
#pragma unroll
            for (int mt = 0; mt < 4; mt++) {
                uint32_t ahp = smem_base + AHI + (uint32_t)((wr * 64 + mt * 16) * ASTR + k0) * 2 + a_lane_off;
                uint32_t alp = ahp + (uint32_t)ALO;
                uint32_t ah[4], al[4];
                ldm_x4(ah, ahp);
                ldm_x4(al, alp);
#pragma unroll
                for (int nt = 0; nt < 4; nt++) {
                    mma_bf16(acc[mt][nt], ah, bh[nt][0], bh[nt][1]);
                    mma_bf16(acc[mt][nt], ah, bl[nt][0], bl[nt][1]);
                    mma_bf16(acc[mt][nt], al, bh[nt][0], bh[nt][1]);
                }
            }
        }
    }

    // ---- epilogue ----
#pragma unroll
    for (int nt = 0; nt < 4; nt++) {
        int col = wc * 32 + nt * 8 + (lane & 3) * 2;
        float bias0 = 0.f, bias1 = 0.f;
        if (LAYER == 1) {
            bias0 = __ldg(b1 + col);
            bias1 = __ldg(b1 + col + 1);
        } else if (LAYER == 2 && col >= 64) {
            bias0 = __ldg(b2 + col - 64);
            bias1 = __ldg(b2 + col - 63);
        }
#pragma unroll
        for (int mt = 0; mt < 4; mt++) {
            int row0 = mbase + wr * 64 + mt * 16 + (lane >> 2);
#pragma unroll
            for (int hrow = 0; hrow < 2; hrow++) {
                int row = row0 + hrow * 8;
                if (row < NN) {
                    float v0 = acc[mt][nt][hrow * 2];
                    float v1 = acc[mt][nt][hrow * 2 + 1];
                    if (LAYER == 0) {
                        *(float2*)(g_xr + (size_t)row * 128 + col) = make_float2(v0, v1);
                    } else if (LAYER == 1) {
                        float2 xr = *(const float2*)(g_xr + (size_t)row * 128 + col);
                        v0 = fmaxf(v0 + xr.x + bias0, 0.f);
                        v1 = fmaxf(v1 + xr.y + bias1, 0.f);
                        uint32_t hi, lo;
                        split_pack(v0, v1, hi, lo);
                        g_hhi[(size_t)row * 64 + (col >> 1)] = hi;
                        g_hlo[(size_t)row * 64 + (col >> 1)] = lo;
                    } else {
                        if (col < 64) {
                            g_pbf[(size_t)row * 32 + (col >> 1)] = pack_bf16x2(v0, v1);
                        } else {
                            *(float2*)(g_q + (size_t)row * 64 + (col - 64)) =
                                make_float2(v0 + bias0, v1 + bias1);
                        }
                    }
                }
            }
        }
    }
}

// ======================= final: log_softmax(mean_agg(P) + Q) =======================
__global__ void k_final(float* __restrict__ out) {
    int node = blockIdx.x * (blockDim.x >> 5) + (threadIdx.x >> 5);
    if (node >= NN) return;
    int lane = threadIdx.x & 31;
    int b = g_rowptr[node], e = g_rowptr[node + 1];
    float a0 = 0.f, a1 = 0.f;
    int i = b;
    for (; i + 4 <= e; i += 4) {
        int u0 = g_col[i + 0], u1 = g_col[i + 1], u2 = g_col[i + 2], u3 = g_col[i + 3];
        uint32_t w0 = g_pbf[(size_t)u0 * 32 + lane];
        uint32_t w1 = g_pbf[(size_t)u1 * 32 + lane];
        uint32_t w2 = g_pbf[(size_t)u2 * 32 + lane];
        uint32_t w3 = g_pbf[(size_t)u3 * 32 + lane];
        a0 += __uint_as_float(w0 << 16) + __uint_as_float(w1 << 16)
            + __uint_as_float(w2 << 16) + __uint_as_float(w3 << 16);
        a1 += __uint_as_float(w0 & 0xffff0000u) + __uint_as_float(w1 & 0xffff0000u)
            + __uint_as_float(w2 & 0xffff0000u) + __uint_as_float(w3 & 0xffff0000u);
    }
    for (; i < e; i++) {
        uint32_t w = g_pbf[(size_t)g_col[i] * 32 + lane];
        a0 += __uint_as_float(w << 16);
        a1 += __uint_as_float(w & 0xffff0000u);
    }
    float inv = 1.f / (float)max(e - b, 1);
    float2 q = *((const float2*)(g_q + (size_t)node * 64) + lane);
    float r0 = a0 * inv + q.x;
    float r1 = a1 * inv + q.y;

    float mx = fmaxf(r0, r1);
#pragma unroll
    for (int off = 16; off > 0; off >>= 1)
        mx = fmaxf(mx, __shfl_xor_sync(0xffffffffu, mx, off));
    float se = expf(r0 - mx) + expf(r1 - mx);
#pragma unroll
    for (int off = 16; off > 0; off >>= 1)
        se += __shfl_xor_sync(0xffffffffu, se, off);
    float l = logf(se);
    float2 o = make_float2(r0 - mx - l, r1 - mx - l);
    *((float2*)(out + (size_t)node * CC) + lane) = o;
}

// ======================= launch =======================
extern "C" void kernel_launch(void* const* d_in, const int* in_sizes, int n_in,
                              void* d_out, int out_size) {
    const float* x   = (const float*)d_in[0];
    const int*   ei  = (const int*)d_in[1];
    const int*   src = ei;
    const int*   dst = ei + NE;
    const float* W1l = (const float*)d_in[2];
    const float* b1l = (const float*)d_in[3];
    const float* W1r = (const float*)d_in[4];
    const float* W2l = (const float*)d_in[5];
    const float* b2l = (const float*)d_in[6];
    const float* W2r = (const float*)d_in[7];
    float* out = (float*)d_out;

    const int SMEM = 106496;
    static cudaStream_t s2 = nullptr, s3 = nullptr;
    static cudaEvent_t evF = nullptr, evJ = nullptr, evFill = nullptr, evB = nullptr, evX = nullptr;
    if (!s2) {
        cudaStreamCreateWithFlags(&s2, cudaStreamNonBlocking);
        cudaStreamCreateWithFlags(&s3, cudaStreamNonBlocking);
        cudaEventCreateWithFlags(&evF, cudaEventDisableTiming);
        cudaEventCreateWithFlags(&evJ, cudaEventDisableTiming);
        cudaEventCreateWithFlags(&evFill, cudaEventDisableTiming);
        cudaEventCreateWithFlags(&evB, cudaEventDisableTiming);
        cudaEventCreateWithFlags(&evX, cudaEventDisableTiming);
        cudaFuncSetAttribute(k_mmagemm<0>, cudaFuncAttributeMaxDynamicSharedMemorySize, SMEM);
        cudaFuncSetAttribute(k_mmagemm<1>, cudaFuncAttributeMaxDynamicSharedMemorySize, SMEM);
        cudaFuncSetAttribute(k_mmagemm<2>, cudaFuncAttributeMaxDynamicSharedMemorySize, SMEM);
    }

    // ---- fork ----
    cudaEventRecord(evF, 0);
    cudaStreamWaitEvent(s2, evF, 0);
    cudaStreamWaitEvent(s3, evF, 0);

    // s2: prepW + xr = x @ W1r^T (tensor-heavy, overlaps CSR build)
    k_prepW<<<(128 * 256 + 128 * 128 + 255) / 256, 256, 0, s2>>>(W1l, W1r, W2l, W2r);
    k_mmagemm<0><<<(NN + 127) / 128, 256, SMEM, s2>>>(x, b1l, b2l, 0);
    cudaEventRecord(evJ, s2);

    // s3: x -> packed bf16 (overlaps count/scan)
    k_xconv<<<(NN * 64 + 255) / 256, 256, 0, s3>>>(x);
    cudaEventRecord(evX, s3);

    // ---- main chain: CSR build ----
    k_count<<<(NE + 255) / 256, 256>>>(dst);
    k_scan1<<<SCAN_NB, SCAN_B>>>();
    k_scan2<<<1, 128>>>();
    k_scan3<<<SCAN_NB, SCAN_B>>>();
    k_fill<<<(NE + 255) / 256, 256>>>(src, dst);
    cudaEventRecord(evFill, 0);

    // ---- chunk 1 on s3: agg1 -> gemm1_1 -> gemm2_1 ----
    cudaStreamWaitEvent(s3, evFill, 0);
    k_agg128<<<(C1N + 7) / 8, 256, 0, s3>>>(C0N, C1N);
    cudaStreamWaitEvent(s3, evJ, 0);
    k_mmagemm<1><<<C1B, 256, SMEM, s3>>>(x, b1l, b2l, C0N);
    k_mmagemm<2><<<C1B, 256, SMEM, s3>>>(x, b1l, b2l, C0N);
    cudaEventRecord(evB, s3);

    // ---- chunk 0 on main: agg0 -> gemm1_0 -> gemm2_0 ----
    cudaStreamWaitEvent(0, evX, 0);
    k_agg128<<<(C0N + 7) / 8, 256>>>(0, C0N);
    cudaStreamWaitEvent(0, evJ, 0);
    k_mmagemm<1><<<C0B, 256, SMEM>>>(x, b1l, b2l, 0);
    k_mmagemm<2><<<C0B, 256, SMEM>>>(x, b1l, b2l, 0);

    // ---- join chunk 1, then final ----
    cudaStreamWaitEvent(0, evB, 0);
    k_final<<<(NN + 7) / 8, 256>>>(out);
}

// round 9
// speedup vs baseline: 1.0638x; 1.0638x over previous
#include <cuda_runtime.h>
#include <cuda_bf16.h>
#include <cstdint>

#define NN 100000
#define NE 1600000
#define FF 128
#define CC 64
#define SCAN_B 1024
#define SCAN_NB ((NN + SCAN_B - 1) / SCAN_B)   // 98

// ======================= scratch (static device globals) =======================
__device__ int   g_cnt[NN];
__device__ int   g_rowptr[NN + 1];
__device__ int   g_cursor[NN];
__device__ int   g_blksum[SCAN_NB];
__device__ int   g_col[NE];
__device__ uint32_t g_pbf[(size_t)NN * 32];    // P = h@W2l^T as packed bf16x2 (64 cols)
__device__ float g_q[(size_t)NN * 64];         // Q = h@W2r^T + b2l (fp32)
__device__ float g_xr[(size_t)NN * 128];       // x @ W1r^T (computed on side stream)
__device__ uint32_t g_mhi[(size_t)NN * 64];    // mean(x) packed bf16x2 hi
__device__ uint32_t g_mlo[(size_t)NN * 64];    // mean(x) packed bf16x2 lo
// weights as bf16 hi/lo, row-major [n][k]
__device__ unsigned short g_w1hi[128 * 256];
__device__ unsigned short g_w1lo[128 * 256];
__device__ unsigned short g_w2hi[128 * 128];
__device__ unsigned short g_w2lo[128 * 128];

// ======================= small helpers =======================
__device__ __forceinline__ uint32_t smem_to_u32(const void* p) {
    uint32_t a;
    asm("{ .reg .u64 t; cvta.to.shared.u64 t, %1; cvt.u32.u64 %0, t; }" : "=r"(a) : "l"(p));
    return a;
}

__device__ __forceinline__ void ldm_x4(uint32_t* r, uint32_t addr) {
    asm volatile("ldmatrix.sync.aligned.m8n8.x4.shared.b16 {%0,%1,%2,%3}, [%4];"
                 : "=r"(r[0]), "=r"(r[1]), "=r"(r[2]), "=r"(r[3]) : "r"(addr));
}

__device__ __forceinline__ void mma_bf16(float* d, const uint32_t* a, uint32_t b0, uint32_t b1) {
    asm volatile(
        "mma.sync.aligned.m16n8k16.row.col.f32.bf16.bf16.f32 "
        "{%0,%1,%2,%3}, {%4,%5,%6,%7}, {%8,%9}, {%0,%1,%2,%3};"
        : "+f"(d[0]), "+f"(d[1]), "+f"(d[2]), "+f"(d[3])
        : "r"(a[0]), "r"(a[1]), "r"(a[2]), "r"(a[3]), "r"(b0), "r"(b1));
}

__device__ __forceinline__ void split_pack(float a, float b, uint32_t& hi, uint32_t& lo) {
    __nv_bfloat16 ah = __float2bfloat16(a), bh = __float2bfloat16(b);
    float ar = a - __bfloat162float(ah);
    float br = b - __bfloat162float(bh);
    hi = (uint32_t)__bfloat16_as_ushort(ah) | ((uint32_t)__bfloat16_as_ushort(bh) << 16);
    lo = (uint32_t)__bfloat16_as_ushort(__float2bfloat16(ar))
       | ((uint32_t)__bfloat16_as_ushort(__float2bfloat16(br)) << 16);
}

__device__ __forceinline__ uint32_t pack_bf16x2(float a, float b) {
    return (uint32_t)__bfloat16_as_ushort(__float2bfloat16(a))
         | ((uint32_t)__bfloat16_as_ushort(__float2bfloat16(b)) << 16);
}

// ======================= CSR build =======================
__global__ void k_count(const int* __restrict__ dst) {
    int e = blockIdx.x * blockDim.x + threadIdx.x;
    if (e < NE) atomicAdd(&g_cnt[dst[e]], 1);
}

__global__ void k_scan1() {
    __shared__ int sh[SCAN_B];
    int t = threadIdx.x;
    int i = blockIdx.x * SCAN_B + t;
    int v = (i < NN) ? g_cnt[i] : 0;
    if (i < NN) g_cnt[i] = 0;     // re-zero for next replay
    sh[t] = v;
    __syncthreads();
#pragma unroll
    for (int off = 1; off < SCAN_B; off <<= 1) {
        int u = (t >= off) ? sh[t - off] : 0;
        __syncthreads();
        sh[t] += u;
        __syncthreads();
    }
    if (i < NN) g_rowptr[i] = sh[t] - v;
    if (t == SCAN_B - 1) g_blksum[blockIdx.x] = sh[t];
}

__global__ void k_scan2() {
    __shared__ int sh[128];
    int t = threadIdx.x;
    int v = (t < SCAN_NB) ? g_blksum[t] : 0;
    sh[t] = v;
    __syncthreads();
#pragma unroll
    for (int off = 1; off < 128; off <<= 1) {
        int u = (t >= off) ? sh[t - off] : 0;
        __syncthreads();
        sh[t] += u;
        __syncthreads();
    }
    if (t < SCAN_NB) g_blksum[t] = sh[t] - v;
}

__global__ void k_scan3() {
    int i = blockIdx.x * SCAN_B + threadIdx.x;
    if (i < NN) {
        int r = g_rowptr[i] + g_blksum[blockIdx.x];
        g_rowptr[i] = r;
        g_cursor[i] = r;
    }
    if (i == 0) g_rowptr[NN] = NE;
}

__global__ void k_fill(const int* __restrict__ src, const int* __restrict__ dst) {
    int e = blockIdx.x * blockDim.x + threadIdx.x;
    if (e < NE) {
        int d = dst[e];
        int pos = atomicAdd(&g_cursor[d], 1);
        g_col[pos] = src[e];
    }
}

// ======================= aggregation (warp per node, unroll 8) =======================
__global__ void k_agg128(const float* __restrict__ X) {
    int node = blockIdx.x * (blockDim.x >> 5) + (threadIdx.x >> 5);
    if (node >= NN) return;
    int lane = threadIdx.x & 31;
    int b = g_rowptr[node], e = g_rowptr[node + 1];
    float4 acc = make_float4(0.f, 0.f, 0.f, 0.f);
    int i = b;
    for (; i + 8 <= e; i += 8) {
        int u0 = g_col[i + 0], u1 = g_col[i + 1], u2 = g_col[i + 2], u3 = g_col[i + 3];
        int u4 = g_col[i + 4], u5 = g_col[i + 5], u6 = g_col[i + 6], u7 = g_col[i + 7];
        float4 v0 = *((const float4*)(X + (size_t)u0 * FF) + lane);
        float4 v1 = *((const float4*)(X + (size_t)u1 * FF) + lane);
        float4 v2 = *((const float4*)(X + (size_t)u2 * FF) + lane);
        float4 v3 = *((const float4*)(X + (size_t)u3 * FF) + lane);
        float4 v4 = *((const float4*)(X + (size_t)u4 * FF) + lane);
        float4 v5 = *((const float4*)(X + (size_t)u5 * FF) + lane);
        float4 v6 = *((const float4*)(X + (size_t)u6 * FF) + lane);
        float4 v7 = *((const float4*)(X + (size_t)u7 * FF) + lane);
        acc.x += ((v0.x + v1.x) + (v2.x + v3.x)) + ((v4.x + v5.x) + (v6.x + v7.x));
        acc.y += ((v0.y + v1.y) + (v2.y + v3.y)) + ((v4.y + v5.y) + (v6.y + v7.y));
        acc.z += ((v0.z + v1.z) + (v2.z + v3.z)) + ((v4.z + v5.z) + (v6.z + v7.z));
        acc.w += ((v0.w + v1.w) + (v2.w + v3.w)) + ((v4.w + v5.w) + (v6.w + v7.w));
    }
    for (; i < e; i++) {
        int u = g_col[i];
        float4 v = *((const float4*)(X + (size_t)u * FF) + lane);
        acc.x += v.x; acc.y += v.y; acc.z += v.z; acc.w += v.w;
    }
    float inv = 1.f / (float)max(e - b, 1);
    uint32_t h0, l0, h1, l1;
    split_pack(acc.x * inv, acc.y * inv, h0, l0);
    split_pack(acc.z * inv, acc.w * inv, h1, l1);
    *((uint2*)(g_mhi + (size_t)node * 64) + lane) = make_uint2(h0, h1);
    *((uint2*)(g_mlo + (size_t)node * 64) + lane) = make_uint2(l0, l1);
}

// ======================= weight prep =======================
__global__ void k_prepW(const float* __restrict__ W1l, const float* __restrict__ W1r,
                        const float* __restrict__ W2l, const float* __restrict__ W2r) {
    int idx = blockIdx.x * blockDim.x + threadIdx.x;
    if (idx < 128 * 256) {
        int n = idx >> 8, k = idx & 255;
        float w = (k < 128) ? W1l[n * 128 + k] : W1r[n * 128 + (k - 128)];
        __nv_bfloat16 h = __float2bfloat16(w);
        g_w1hi[idx] = __bfloat16_as_ushort(h);
        g_w1lo[idx] = __bfloat16_as_ushort(__float2bfloat16(w - __bfloat162float(h)));
    } else {
        int i2 = idx - 128 * 256;
        if (i2 < 128 * 128) {
            int n = i2 >> 7, k = i2 & 127;
            float w = (n < 64) ? W2l[n * 128 + k] : W2r[(n - 64) * 128 + k];
            __nv_bfloat16 h = __float2bfloat16(w);
            g_w2hi[i2] = __bfloat16_as_ushort(h);
            g_w2lo[i2] = __bfloat16_as_ushort(__float2bfloat16(w - __bfloat162float(h)));
        }
    }
}

// ======================= GEMM 0: xr = x @ W1r^T (side stream) =======================
#define ASTR 72
#define BSTR 136

__global__ void __launch_bounds__(256, 2)
k_gemm0(const float* __restrict__ X)
{
    constexpr int AHI = 0;
    constexpr int ALO = 128 * ASTR * 2;      // 18432
    constexpr int BHI = 2 * 128 * ASTR * 2;  // 36864
    constexpr int BLO = BHI + 128 * BSTR * 2;

    extern __shared__ char smem[];
    const uint32_t smem_base = smem_to_u32(smem);
    const int tid = threadIdx.x, warp = tid >> 5, lane = tid & 31;
    const int wr = warp >> 2, wc = warp & 3;
    const int mbase = blockIdx.x * 128;

    // W1r half (k 128..255) into smem
    for (int i = tid; i < 128 * 16; i += 256) {
        int n = i >> 4, c = i & 15;
        *(uint4*)(smem + BHI + n * (BSTR * 2) + c * 16) = ((const uint4*)g_w1hi)[n * 32 + 16 + c];
        *(uint4*)(smem + BLO + n * (BSTR * 2) + c * 16) = ((const uint4*)g_w1lo)[n * 32 + 16 + c];
    }

    float acc[4][4][4];
#pragma unroll
    for (int mt = 0; mt < 4; mt++)
#pragma unroll
        for (int nt = 0; nt < 4; nt++)
#pragma unroll
            for (int q = 0; q < 4; q++) acc[mt][nt][q] = 0.f;

    const uint32_t a_off = (uint32_t)(((lane & 15) * ASTR + (lane >> 4) * 8) * 2);
    const uint32_t* Bh = (const uint32_t*)(smem + BHI);
    const uint32_t* Bl = (const uint32_t*)(smem + BLO);

#pragma unroll
    for (int ch = 0; ch < 2; ch++) {
        __syncthreads();
        {
            int row = tid >> 1, half = tid & 1;
            int gr = mbase + row;
            bool valid = gr < NN;
            uint32_t* dAh = (uint32_t*)(smem + AHI + row * (ASTR * 2));
            uint32_t* dAl = (uint32_t*)(smem + ALO + row * (ASTR * 2));
            const float* src = X + (size_t)gr * 128 + ch * 64 + half * 32;
#pragma unroll
            for (int j = 0; j < 8; j++) {
                float4 v = make_float4(0.f, 0.f, 0.f, 0.f);
                if (valid) v = *(const float4*)(src + j * 4);
                uint32_t h0, l0, h1, l1;
                split_pack(v.x, v.y, h0, l0);
                split_pack(v.z, v.w, h1, l1);
                int o = half * 16 + j * 2;
                dAh[o] = h0; dAh[o + 1] = h1;
                dAl[o] = l0; dAl[o + 1] = l1;
            }
        }
        __syncthreads();
#pragma unroll
        for (int ks = 0; ks < 4; ks++) {
            const int k0 = ks * 16;
            uint32_t bh[4][2], bl[4][2];
#pragma unroll
            for (int nt = 0; nt < 4; nt++) {
                int n = wc * 32 + nt * 8 + (lane >> 2);
                int bi = n * (BSTR / 2) + (ch * 64 + k0) / 2 + (lane & 3);
                bh[nt][0] = Bh[bi]; bh[nt][1] = Bh[bi + 4];
                bl[nt][0] = Bl[bi]; bl[nt][1] = Bl[bi + 4];
            }
#pragma unroll
            for (int mt = 0; mt < 4; mt++) {
                uint32_t ahp = smem_base + AHI + (uint32_t)((wr * 64 + mt * 16) * ASTR + k0) * 2 + a_off;
                uint32_t ah[4], al[4];
                ldm_x4(ah, ahp);
                ldm_x4(al, ahp + (uint32_t)ALO);
#pragma unroll
                for (int nt = 0; nt < 4; nt++) {
                    mma_bf16(acc[mt][nt], ah, bh[nt][0], bh[nt][1]);
                    mma_bf16(acc[mt][nt], ah, bl[nt][0], bl[nt][1]);
                    mma_bf16(acc[mt][nt], al, bh[nt][0], bh[nt][1]);
                }
            }
        }
    }

#pragma unroll
    for (int nt = 0; nt < 4; nt++) {
        int col = wc * 32 + nt * 8 + (lane & 3) * 2;
#pragma unroll
        for (int mt = 0; mt < 4; mt++) {
            int row0 = mbase + wr * 64 + mt * 16 + (lane >> 2);
#pragma unroll
            for (int hrow = 0; hrow < 2; hrow++) {
                int row = row0 + hrow * 8;
                if (row < NN)
                    *(float2*)(g_xr + (size_t)row * 128 + col) =
                        make_float2(acc[mt][nt][hrow * 2], acc[mt][nt][hrow * 2 + 1]);
            }
        }
    }
}

// ======================= fused GEMM 1+2 =======================
// phase 1: h = relu(mean @ W1l^T + xr + b1)  -> smem H (bf16 hi/lo, stride 136)
// phase 2: P|Q = h @ [W2l;W2r]^T (+b2 hi)    -> g_pbf / g_q
__global__ void __launch_bounds__(256, 1)
k_gemm12(const float* __restrict__ b1, const float* __restrict__ b2)
{
    constexpr int AHI = 0;
    constexpr int ALO = 128 * ASTR * 2;        // 18432
    constexpr int BHI = 2 * 128 * ASTR * 2;    // 36864
    constexpr int BLO = BHI + 128 * BSTR * 2;  // 71680
    constexpr int HHI = BLO + 128 * BSTR * 2;  // 106496
    constexpr int HLO = HHI + 128 * BSTR * 2;  // 141312 ; total 176128

    extern __shared__ char smem[];
    const uint32_t smem_base = smem_to_u32(smem);
    const int tid = threadIdx.x, warp = tid >> 5, lane = tid & 31;
    const int wr = warp >> 2, wc = warp & 3;
    const int mbase = blockIdx.x * 128;

    // ---- W1l half (k 0..127) into B region ----
    for (int i = tid; i < 128 * 16; i += 256) {
        int n = i >> 4, c = i & 15;
        *(uint4*)(smem + BHI + n * (BSTR * 2) + c * 16) = ((const uint4*)g_w1hi)[n * 32 + c];
        *(uint4*)(smem + BLO + n * (BSTR * 2) + c * 16) = ((const uint4*)g_w1lo)[n * 32 + c];
    }

    float acc[4][4][4];
#pragma unroll
    for (int mt = 0; mt < 4; mt++)
#pragma unroll
        for (int nt = 0; nt < 4; nt++)
#pragma unroll
            for (int q = 0; q < 4; q++) acc[mt][nt][q] = 0.f;

    const uint32_t a_off1 = (uint32_t)(((lane & 15) * ASTR + (lane >> 4) * 8) * 2);
    const uint32_t a_off2 = (uint32_t)(((lane & 15) * BSTR + (lane >> 4) * 8) * 2);
    const uint32_t* Bh = (const uint32_t*)(smem + BHI);
    const uint32_t* Bl = (const uint32_t*)(smem + BLO);

    // ---- mainloop 1: mean @ W1l^T ----
#pragma unroll
    for (int ch = 0; ch < 2; ch++) {
        __syncthreads();
        {
            int row = tid >> 1, half = tid & 1;
            int gr = mbase + row;
            bool valid = gr < NN;
            uint32_t* dAh = (uint32_t*)(smem + AHI + row * (ASTR * 2));
            uint32_t* dAl = (uint32_t*)(smem + ALO + row * (ASTR * 2));
            size_t off = (size_t)gr * 64 + ch * 32 + half * 16;
#pragma unroll
            for (int j = 0; j < 4; j++) {
                uint4 vh = make_uint4(0u, 0u, 0u, 0u), vl = vh;
                if (valid) {
                    vh = *(const uint4*)(g_mhi + off + j * 4);
                    vl = *(const uint4*)(g_mlo + off + j * 4);
                }
                *(uint4*)(dAh + half * 16 + j * 4) = vh;
                *(uint4*)(dAl + half * 16 + j * 4) = vl;
            }
        }
        __syncthreads();
#pragma unroll
        for (int ks = 0; ks < 4; ks++) {
            const int k0 = ks * 16;
            uint32_t bh[4][2], bl[4][2];
#pragma unroll
            for (int nt = 0; nt < 4; nt++) {
                int n = wc * 32 + nt * 8 + (lane >> 2);
                int bi = n * (BSTR / 2) + (ch * 64 + k0) / 2 + (lane & 3);
                bh[nt][0] = Bh[bi]; bh[nt][1] = Bh[bi + 4];
                bl[nt][0] = Bl[bi]; bl[nt][1] = Bl[bi + 4];
            }
#pragma unroll
            for (int mt = 0; mt < 4; mt++) {
                uint32_t ahp = smem_base + AHI + (uint32_t)((wr * 64 + mt * 16) * ASTR + k0) * 2 + a_off1;
                uint32_t ah[4], al[4];
                ldm_x4(ah, ahp);
                ldm_x4(al, ahp + (uint32_t)ALO);
#pragma unroll
                for (int nt = 0; nt < 4; nt++) {
                    mma_bf16(acc[mt][nt], ah, bh[nt][0], bh[nt][1]);
                    mma_bf16(acc[mt][nt], ah, bl[nt][0], bl[nt][1]);
                    mma_bf16(acc[mt][nt], al, bh[nt][0], bh[nt][1]);
                }
            }
        }
    }

    // ---- epilogue 1: h -> smem H (bf16 hi/lo) ----
#pragma unroll
    for (int nt = 0; nt < 4; nt++) {
        int col = wc * 32 + nt * 8 + (lane & 3) * 2;
        float bias0 = __ldg(b1 + col);
        float bias1 = __ldg(b1 + col + 1);
#pragma unroll
        for (int mt = 0; mt < 4; mt++) {
            int rl0 = wr * 64 + mt * 16 + (lane >> 2);
#pragma unroll
            for (int hrow = 0; hrow < 2; hrow++) {
                int rl = rl0 + hrow * 8;
                int grow = mbase + rl;
                float2 xr = make_float2(0.f, 0.f);
                if (grow < NN) xr = *(const float2*)(g_xr + (size_t)grow * 128 + col);
                float v0 = fmaxf(acc[mt][nt][hrow * 2]     + xr.x + bias0, 0.f);
                float v1 = fmaxf(acc[mt][nt][hrow * 2 + 1] + xr.y + bias1, 0.f);
                uint32_t hi, lo;
                split_pack(v0, v1, hi, lo);
                *(uint32_t*)(smem + HHI + rl * (BSTR * 2) + (col >> 1) * 4) = hi;
                *(uint32_t*)(smem + HLO + rl * (BSTR * 2) + (col >> 1) * 4) = lo;
            }
        }
    }
    __syncthreads();

    // ---- W2 into B region (overwrite W1) ----
    for (int i = tid; i < 128 * 16; i += 256) {
        int n = i >> 4, c = i & 15;
        *(uint4*)(smem + BHI + n * (BSTR * 2) + c * 16) = ((const uint4*)g_w2hi)[n * 16 + c];
        *(uint4*)(smem + BLO + n * (BSTR * 2) + c * 16) = ((const uint4*)g_w2lo)[n * 16 + c];
    }
#pragma unroll
    for (int mt = 0; mt < 4; mt++)
#pragma unroll
        for (int nt = 0; nt < 4; nt++)
#pragma unroll
            for (int q = 0; q < 4; q++) acc[mt][nt][q] = 0.f;
    __syncthreads();

    // ---- mainloop 2: h @ W2^T (A = smem H, full K=128) ----
#pragma unroll
    for (int ks = 0; ks < 8; ks++) {
        const int k0 = ks * 16;
        uint32_t bh[4][2], bl[4][2];
#pragma unroll
        for (int nt = 0; nt < 4; nt++) {
            int n = wc * 32 + nt * 8 + (lane >> 2);
            int bi = n * (BSTR / 2) + k0 / 2 + (lane & 3);
            bh[nt][0] = Bh[bi]; bh[nt][1] = Bh[bi + 4];
            bl[nt][0] = Bl[bi]; bl[nt][1] = Bl[bi + 4];
        }
#pragma unroll
        for (int mt = 0; mt < 4; mt++) {
            uint32_t ahp = smem_base + HHI + (uint32_t)((wr * 64 + mt * 16) * BSTR + k0) * 2 + a_off2;
            uint32_t ah[4], al[4];
            ldm_x4(ah, ahp);
            ldm_x4(al, ahp + (uint32_t)(HLO - HHI));
#pragma unroll
            for (int nt = 0; nt < 4; nt++) {
                mma_bf16(acc[mt][nt], ah, bh[nt][0], bh[nt][1]);
                mma_bf16(acc[mt][nt], ah, bl[nt][0], bl[nt][1]);
                mma_bf16(acc[mt][nt], al, bh[nt][0], bh[nt][1]);
            }
        }
    }

    // ---- epilogue 2: P bf16 / Q fp32 ----
#pragma unroll
    for (int nt = 0; nt < 4; nt++) {
        int col = wc * 32 + nt * 8 + (lane & 3) * 2;
        float bias0 = 0.f, bias1 = 0.f;
        if (col >= 64) {
            bias0 = __ldg(b2 + col - 64);
            bias1 = __ldg(b2 + col - 63);
        }
#pragma unroll
        for (int mt = 0; mt < 4; mt++) {
            int row0 = mbase + wr * 64 + mt * 16 + (lane >> 2);
#pragma unroll
            for (int hrow = 0; hrow < 2; hrow++) {
                int row = row0 + hrow * 8;
                if (row < NN) {
                    float v0 = acc[mt][nt][hrow * 2];
                    float v1 = acc[mt][nt][hrow * 2 + 1];
                    if (col < 64) {
                        g_pbf[(size_t)row * 32 + (col >> 1)] = pack_bf16x2(v0, v1);
                    } else {
                        *(float2*)(g_q + (size_t)row * 64 + (col - 64)) =
                            make_float2(v0 + bias0, v1 + bias1);
                    }
                }
            }
        }
    }
}

// ======================= final: log_softmax(mean_agg(P) + Q) =======================
__global__ void k_final(float* __restrict__ out) {
    int node = blockIdx.x * (blockDim.x >> 5) + (threadIdx.x >> 5);
    if (node >= NN) return;
    int lane = threadIdx.x & 31;
    int b = g_rowptr[node], e = g_rowptr[node + 1];
    float a0 = 0.f, a1 = 0.f;
    int i = b;
    for (; i + 4 <= e; i += 4) {
        int u0 = g_col[i + 0], u1 = g_col[i + 1], u2 = g_col[i + 2], u3 = g_col[i + 3];
        uint32_t w0 = g_pbf[(size_t)u0 * 32 + lane];
        uint32_t w1 = g_pbf[(size_t)u1 * 32 + lane];
        uint32_t w2 = g_pbf[(size_t)u2 * 32 + lane];
        uint32_t w3 = g_pbf[(size_t)u3 * 32 + lane];
        a0 += __uint_as_float(w0 << 16) + __uint_as_float(w1 << 16)
            + __uint_as_float(w2 << 16) + __uint_as_float(w3 << 16);
        a1 += __uint_as_float(w0 & 0xffff0000u) + __uint_as_float(w1 & 0xffff0000u)
            + __uint_as_float(w2 & 0xffff0000u) + __uint_as_float(w3 & 0xffff0000u);
    }
    for (; i < e; i++) {
        uint32_t w = g_pbf[(size_t)g_col[i] * 32 + lane];
        a0 += __uint_as_float(w << 16);
        a1 += __uint_as_float(w & 0xffff0000u);
    }
    float inv = 1.f / (float)max(e - b, 1);
    float2 q = *((const float2*)(g_q + (size_t)node * 64) + lane);
    float r0 = a0 * inv + q.x;
    float r1 = a1 * inv + q.y;

    float mx = fmaxf(r0, r1);
#pragma unroll
    for (int off = 16; off > 0; off >>= 1)
        mx = fmaxf(mx, __shfl_xor_sync(0xffffffffu, mx, off));
    float se = expf(r0 - mx) + expf(r1 - mx);
#pragma unroll
    for (int off = 16; off > 0; off >>= 1)
        se += __shfl_xor_sync(0xffffffffu, se, off);
    float l = logf(se);
    float2 o = make_float2(r0 - mx - l, r1 - mx - l);
    *((float2*)(out + (size_t)node * CC) + lane) = o;
}

// ======================= launch =======================
extern "C" void kernel_launch(void* const* d_in, const int* in_sizes, int n_in,
                              void* d_out, int out_size) {
    const float* x   = (const float*)d_in[0];
    const int*   ei  = (const int*)d_in[1];
    const int*   src = ei;
    const int*   dst = ei + NE;
    const float* W1l = (const float*)d_in[2];
    const float* b1l = (const float*)d_in[3];
    const float* W1r = (const float*)d_in[4];
    const float* W2l = (const float*)d_in[5];
    const float* b2l = (const float*)d_in[6];
    const float* W2r = (const float*)d_in[7];
    float* out = (float*)d_out;

    const int SMEM0  = 106496;
    const int SMEM12 = 176128;
    static cudaStream_t s2 = nullptr;
    static cudaEvent_t evF = nullptr, evJ = nullptr;
    if (!s2) {
        cudaStreamCreateWithFlags(&s2, cudaStreamNonBlocking);
        cudaEventCreateWithFlags(&evF, cudaEventDisableTiming);
        cudaEventCreateWithFlags(&evJ, cudaEventDisableTiming);
        cudaFuncSetAttribute(k_gemm0,  cudaFuncAttributeMaxDynamicSharedMemorySize, SMEM0);
        cudaFuncSetAttribute(k_gemm12, cudaFuncAttributeMaxDynamicSharedMemorySize, SMEM12);
    }

    const int NB = (NN + 127) / 128;

    // ---- fork: side stream computes prepW + xr = x @ W1r^T ----
    cudaEventRecord(evF, 0);
    cudaStreamWaitEvent(s2, evF, 0);
    k_prepW<<<(128 * 256 + 128 * 128 + 255) / 256, 256, 0, s2>>>(W1l, W1r, W2l, W2r);
    k_gemm0<<<NB, 256, SMEM0, s2>>>(x);
    cudaEventRecord(evJ, s2);

    // ---- main chain: CSR build + aggregation ----
    k_count<<<(NE + 255) / 256, 256>>>(dst);
    k_scan1<<<SCAN_NB, SCAN_B>>>();
    k_scan2<<<1, 128>>>();
    k_scan3<<<SCAN_NB, SCAN_B>>>();
    k_fill<<<(NE + 255) / 256, 256>>>(src, dst);
    k_agg128<<<(NN + 7) / 8, 256>>>(x);          // g_mhi/g_mlo = mean(x) splits

    // ---- join, fused GEMM, final ----
    cudaStreamWaitEvent(0, evJ, 0);
    k_gemm12<<<NB, 256, SMEM12>>>(b1l, b2l);     // h in smem -> P|Q
    k_final<<<(NN + 7) / 8, 256>>>(out);
}

// round 10
// speedup vs baseline: 1.3992x; 1.3153x over previous
#include <cuda_runtime.h>
#include <cuda_bf16.h>
#include <cstdint>

#define NN 100000
#define NE 1600000
#define FF 128
#define CC 64
#define SCAN_B 1024
#define SCAN_NB ((NN + SCAN_B - 1) / SCAN_B)   // 98

// ======================= scratch (static device globals) =======================
__device__ int   g_cnt[NN];
__device__ int   g_rowptr[NN + 1];
__device__ int   g_cursor[NN];
__device__ int   g_blksum[SCAN_NB];
__device__ int   g_col[NE];
__device__ uint32_t g_xbf[(size_t)NN * 64];    // x packed bf16x2
__device__ uint32_t g_m[(size_t)NN * 64];      // mean(x) packed bf16x2
__device__ uint32_t g_xrbf[(size_t)NN * 64];   // xr = x @ W1r^T packed bf16x2
__device__ uint32_t g_pbf[(size_t)NN * 32];    // P = h@W2l^T packed bf16x2
__device__ float g_q[(size_t)NN * 64];         // Q = h@W2r^T + b2l (fp32)
// weights as plain bf16, row-major [n][k]
__device__ unsigned short g_w1[128 * 256];     // [W1l | W1r]
__device__ unsigned short g_w2[128 * 128];     // [W2l ; W2r]

// ======================= small helpers =======================
__device__ __forceinline__ uint32_t smem_to_u32(const void* p) {
    uint32_t a;
    asm("{ .reg .u64 t; cvta.to.shared.u64 t, %1; cvt.u32.u64 %0, t; }" : "=r"(a) : "l"(p));
    return a;
}

__device__ __forceinline__ void ldm_x4(uint32_t* r, uint32_t addr) {
    asm volatile("ldmatrix.sync.aligned.m8n8.x4.shared.b16 {%0,%1,%2,%3}, [%4];"
                 : "=r"(r[0]), "=r"(r[1]), "=r"(r[2]), "=r"(r[3]) : "r"(addr));
}

__device__ __forceinline__ void mma_bf16(float* d, const uint32_t* a, uint32_t b0, uint32_t b1) {
    asm volatile(
        "mma.sync.aligned.m16n8k16.row.col.f32.bf16.bf16.f32 "
        "{%0,%1,%2,%3}, {%4,%5,%6,%7}, {%8,%9}, {%0,%1,%2,%3};"
        : "+f"(d[0]), "+f"(d[1]), "+f"(d[2]), "+f"(d[3])
        : "r"(a[0]), "r"(a[1]), "r"(a[2]), "r"(a[3]), "r"(b0), "r"(b1));
}

__device__ __forceinline__ uint32_t pack_bf16x2(float a, float b) {
    return (uint32_t)__bfloat16_as_ushort(__float2bfloat16(a))
         | ((uint32_t)__bfloat16_as_ushort(__float2bfloat16(b)) << 16);
}

__device__ __forceinline__ float bf_lo(uint32_t w) { return __uint_as_float(w << 16); }
__device__ __forceinline__ float bf_hi(uint32_t w) { return __uint_as_float(w & 0xffff0000u); }

// ======================= CSR build =======================
__global__ void k_count(const int* __restrict__ dst) {
    int e = blockIdx.x * blockDim.x + threadIdx.x;
    if (e < NE) atomicAdd(&g_cnt[dst[e]], 1);
}

__global__ void k_scan1() {
    __shared__ int sh[SCAN_B];
    int t = threadIdx.x;
    int i = blockIdx.x * SCAN_B + t;
    int v = (i < NN) ? g_cnt[i] : 0;
    if (i < NN) g_cnt[i] = 0;     // re-zero for next replay
    sh[t] = v;
    __syncthreads();
#pragma unroll
    for (int off = 1; off < SCAN_B; off <<= 1) {
        int u = (t >= off) ? sh[t - off] : 0;
        __syncthreads();
        sh[t] += u;
        __syncthreads();
    }
    if (i < NN) g_rowptr[i] = sh[t] - v;
    if (t == SCAN_B - 1) g_blksum[blockIdx.x] = sh[t];
}

__global__ void k_scan2() {
    __shared__ int sh[128];
    int t = threadIdx.x;
    int v = (t < SCAN_NB) ? g_blksum[t] : 0;
    sh[t] = v;
    __syncthreads();
#pragma unroll
    for (int off = 1; off < 128; off <<= 1) {
        int u = (t >= off) ? sh[t - off] : 0;
        __syncthreads();
        sh[t] += u;
        __syncthreads();
    }
    if (t < SCAN_NB) g_blksum[t] = sh[t] - v;
}

__global__ void k_scan3() {
    int i = blockIdx.x * SCAN_B + threadIdx.x;
    if (i < NN) {
        int r = g_rowptr[i] + g_blksum[blockIdx.x];
        g_rowptr[i] = r;
        g_cursor[i] = r;
    }
    if (i == 0) g_rowptr[NN] = NE;
}

__global__ void k_fill(const int* __restrict__ src, const int* __restrict__ dst) {
    int e = blockIdx.x * blockDim.x + threadIdx.x;
    if (e < NE) {
        int d = dst[e];
        int pos = atomicAdd(&g_cursor[d], 1);
        g_col[pos] = src[e];
    }
}

// ======================= x -> packed bf16 =======================
__global__ void k_xconv(const float* __restrict__ X) {
    int i = blockIdx.x * blockDim.x + threadIdx.x;
    if (i < NN * 64) {
        float2 v = *(const float2*)(X + (size_t)i * 2);
        g_xbf[i] = pack_bf16x2(v.x, v.y);
    }
}

// ======================= aggregation (warp per node, bf16 gather, unroll 8) =======
__global__ void k_agg128() {
    int node = blockIdx.x * (blockDim.x >> 5) + (threadIdx.x >> 5);
    if (node >= NN) return;
    int lane = threadIdx.x & 31;
    int b = g_rowptr[node], e = g_rowptr[node + 1];
    float a0 = 0.f, a1 = 0.f, a2 = 0.f, a3 = 0.f;
    int i = b;
    for (; i + 8 <= e; i += 8) {
        int u0 = g_col[i + 0], u1 = g_col[i + 1], u2 = g_col[i + 2], u3 = g_col[i + 3];
        int u4 = g_col[i + 4], u5 = g_col[i + 5], u6 = g_col[i + 6], u7 = g_col[i + 7];
        uint2 w0 = *((const uint2*)(g_xbf + (size_t)u0 * 64) + lane);
        uint2 w1 = *((const uint2*)(g_xbf + (size_t)u1 * 64) + lane);
        uint2 w2 = *((const uint2*)(g_xbf + (size_t)u2 * 64) + lane);
        uint2 w3 = *((const uint2*)(g_xbf + (size_t)u3 * 64) + lane);
        uint2 w4 = *((const uint2*)(g_xbf + (size_t)u4 * 64) + lane);
        uint2 w5 = *((const uint2*)(g_xbf + (size_t)u5 * 64) + lane);
        uint2 w6 = *((const uint2*)(g_xbf + (size_t)u6 * 64) + lane);
        uint2 w7 = *((const uint2*)(g_xbf + (size_t)u7 * 64) + lane);
        a0 += ((bf_lo(w0.x) + bf_lo(w1.x)) + (bf_lo(w2.x) + bf_lo(w3.x)))
            + ((bf_lo(w4.x) + bf_lo(w5.x)) + (bf_lo(w6.x) + bf_lo(w7.x)));
        a1 += ((bf_hi(w0.x) + bf_hi(w1.x)) + (bf_hi(w2.x) + bf_hi(w3.x)))
            + ((bf_hi(w4.x) + bf_hi(w5.x)) + (bf_hi(w6.x) + bf_hi(w7.x)));
        a2 += ((bf_lo(w0.y) + bf_lo(w1.y)) + (bf_lo(w2.y) + bf_lo(w3.y)))
            + ((bf_lo(w4.y) + bf_lo(w5.y)) + (bf_lo(w6.y) + bf_lo(w7.y)));
        a3 += ((bf_hi(w0.y) + bf_hi(w1.y)) + (bf_hi(w2.y) + bf_hi(w3.y)))
            + ((bf_hi(w4.y) + bf_hi(w5.y)) + (bf_hi(w6.y) + bf_hi(w7.y)));
    }
    for (; i < e; i++) {
        uint2 w = *((const uint2*)(g_xbf + (size_t)g_col[i] * 64) + lane);
        a0 += bf_lo(w.x); a1 += bf_hi(w.x);
        a2 += bf_lo(w.y); a3 += bf_hi(w.y);
    }
    float inv = 1.f / (float)max(e - b, 1);
    *((uint2*)(g_m + (size_t)node * 64) + lane) =
        make_uint2(pack_bf16x2(a0 * inv, a1 * inv), pack_bf16x2(a2 * inv, a3 * inv));
}

// ======================= weight prep (plain bf16) =======================
__global__ void k_prepW(const float* __restrict__ W1l, const float* __restrict__ W1r,
                        const float* __restrict__ W2l, const float* __restrict__ W2r) {
    int idx = blockIdx.x * blockDim.x + threadIdx.x;
    if (idx < 128 * 256) {
        int n = idx >> 8, k = idx & 255;
        float w = (k < 128) ? W1l[n * 128 + k] : W1r[n * 128 + (k - 128)];
        g_w1[idx] = __bfloat16_as_ushort(__float2bfloat16(w));
    } else {
        int i2 = idx - 128 * 256;
        if (i2 < 128 * 128) {
            int n = i2 >> 7, k = i2 & 127;
            float w = (n < 64) ? W2l[n * 128 + k] : W2r[(n - 64) * 128 + k];
            g_w2[i2] = __bfloat16_as_ushort(__float2bfloat16(w));
        }
    }
}

// ======================= single-term bf16 HMMA GEMMs =======================
#define BSTR 136   // bf16 per smem row (272B: conflict-free ldmatrix/frag access)

// GEMM 0 (side stream): xr = x @ W1r^T  -> g_xrbf packed bf16
__global__ void __launch_bounds__(256, 2)
k_gemm0()
{
    constexpr int AOFF = 0;
    constexpr int BOFF = 128 * BSTR * 2;   // 34816
    // smem total 69632
    extern __shared__ char smem[];
    const uint32_t smem_base = smem_to_u32(smem);
    const int tid = threadIdx.x, warp = tid >> 5, lane = tid & 31;
    const int wr = warp >> 2, wc = warp & 3;
    const int mbase = blockIdx.x * 128;

    // B: W1 cols 128..255 (W1r)
    for (int i = tid; i < 128 * 16; i += 256) {
        int n = i >> 4, c = i & 15;
        *(uint4*)(smem + BOFF + n * (BSTR * 2) + c * 16) = ((const uint4*)g_w1)[n * 32 + 16 + c];
    }
    // A: full 128-row x 128-k tile from g_xbf
    {
        int row = tid >> 1, half = tid & 1;
        int gr = mbase + row;
        bool valid = gr < NN;
        const uint4* src = (const uint4*)(g_xbf + (size_t)gr * 64 + half * 32);
        char* dA = smem + AOFF + row * (BSTR * 2) + half * 128;
#pragma unroll
        for (int j = 0; j < 8; j++) {
            uint4 v = make_uint4(0u, 0u, 0u, 0u);
            if (valid) v = src[j];
            *(uint4*)(dA + j * 16) = v;
        }
    }
    __syncthreads();

    float acc[4][4][4];
#pragma unroll
    for (int mt = 0; mt < 4; mt++)
#pragma unroll
        for (int nt = 0; nt < 4; nt++)
#pragma unroll
            for (int q = 0; q < 4; q++) acc[mt][nt][q] = 0.f;

    const uint32_t a_off = (uint32_t)(((lane & 15) * BSTR + (lane >> 4) * 8) * 2);
    const uint32_t* Bp = (const uint32_t*)(smem + BOFF);

#pragma unroll
    for (int ks = 0; ks < 8; ks++) {
        const int k0 = ks * 16;
        uint32_t bf[4][2];
#pragma unroll
        for (int nt = 0; nt < 4; nt++) {
            int n = wc * 32 + nt * 8 + (lane >> 2);
            int bi = n * (BSTR / 2) + k0 / 2 + (lane & 3);
            bf[nt][0] = Bp[bi]; bf[nt][1] = Bp[bi + 4];
        }
#pragma unroll
        for (int mt = 0; mt < 4; mt++) {
            uint32_t ahp = smem_base + AOFF + (uint32_t)((wr * 64 + mt * 16) * BSTR + k0) * 2 + a_off;
            uint32_t ah[4];
            ldm_x4(ah, ahp);
#pragma unroll
            for (int nt = 0; nt < 4; nt++)
                mma_bf16(acc[mt][nt], ah, bf[nt][0], bf[nt][1]);
        }
    }

#pragma unroll
    for (int nt = 0; nt < 4; nt++) {
        int col = wc * 32 + nt * 8 + (lane & 3) * 2;
#pragma unroll
        for (int mt = 0; mt < 4; mt++) {
            int row0 = mbase + wr * 64 + mt * 16 + (lane >> 2);
#pragma unroll
            for (int hrow = 0; hrow < 2; hrow++) {
                int row = row0 + hrow * 8;
                if (row < NN)
                    g_xrbf[(size_t)row * 64 + (col >> 1)] =
                        pack_bf16x2(acc[mt][nt][hrow * 2], acc[mt][nt][hrow * 2 + 1]);
            }
        }
    }
}

// fused GEMM 1+2:
//   phase 1: h = relu(mean @ W1l^T + xr + b1) -> smem H (bf16)
//   phase 2: P|Q = h @ [W2l;W2r]^T (+b2 hi)   -> g_pbf / g_q
__global__ void __launch_bounds__(256, 2)
k_gemm12(const float* __restrict__ b1, const float* __restrict__ b2)
{
    constexpr int AOFF = 0;
    constexpr int BOFF = 128 * BSTR * 2;       // 34816
    constexpr int HOFF = 2 * 128 * BSTR * 2;   // 69632 ; total 104448
    extern __shared__ char smem[];
    const uint32_t smem_base = smem_to_u32(smem);
    const int tid = threadIdx.x, warp = tid >> 5, lane = tid & 31;
    const int wr = warp >> 2, wc = warp & 3;
    const int mbase = blockIdx.x * 128;

    // B: W1 cols 0..127 (W1l)
    for (int i = tid; i < 128 * 16; i += 256) {
        int n = i >> 4, c = i & 15;
        *(uint4*)(smem + BOFF + n * (BSTR * 2) + c * 16) = ((const uint4*)g_w1)[n * 32 + c];
    }
    // A: mean tile
    {
        int row = tid >> 1, half = tid & 1;
        int gr = mbase + row;
        bool valid = gr < NN;
        const uint4* src = (const uint4*)(g_m + (size_t)gr * 64 + half * 32);
        char* dA = smem + AOFF + row * (BSTR * 2) + half * 128;
#pragma unroll
        for (int j = 0; j < 8; j++) {
            uint4 v = make_uint4(0u, 0u, 0u, 0u);
            if (valid) v = src[j];
            *(uint4*)(dA + j * 16) = v;
        }
    }
    __syncthreads();

    float acc[4][4][4];
#pragma unroll
    for (int mt = 0; mt < 4; mt++)
#pragma unroll
        for (int nt = 0; nt < 4; nt++)
#pragma unroll
            for (int q = 0; q < 4; q++) acc[mt][nt][q] = 0.f;

    const uint32_t a_off = (uint32_t)(((lane & 15) * BSTR + (lane >> 4) * 8) * 2);
    const uint32_t* Bp = (const uint32_t*)(smem + BOFF);

    // ---- mainloop 1 ----
#pragma unroll
    for (int ks = 0; ks < 8; ks++) {
        const int k0 = ks * 16;
        uint32_t bf[4][2];
#pragma unroll
        for (int nt = 0; nt < 4; nt++) {
            int n = wc * 32 + nt * 8 + (lane >> 2);
            int bi = n * (BSTR / 2) + k0 / 2 + (lane & 3);
            bf[nt][0] = Bp[bi]; bf[nt][1] = Bp[bi + 4];
        }
#pragma unroll
        for (int mt = 0; mt < 4; mt++) {
            uint32_t ahp = smem_base + AOFF + (uint32_t)((wr * 64 + mt * 16) * BSTR + k0) * 2 + a_off;
            uint32_t ah[4];
            ldm_x4(ah, ahp);
#pragma unroll
            for (int nt = 0; nt < 4; nt++)
                mma_bf16(acc[mt][nt], ah, bf[nt][0], bf[nt][1]);
        }
    }

    // ---- epilogue 1: h -> smem H (bf16) ----
#pragma unroll
    for (int nt = 0; nt < 4; nt++) {
        int col = wc * 32 + nt * 8 + (lane & 3) * 2;
        float bias0 = __ldg(b1 + col);
        float bias1 = __ldg(b1 + col + 1);
#pragma unroll
        for (int mt = 0; mt < 4; mt++) {
            int rl0 = wr * 64 + mt * 16 + (lane >> 2);
#pragma unroll
            for (int hrow = 0; hrow < 2; hrow++) {
                int rl = rl0 + hrow * 8;
                int grow = mbase + rl;
                float xr0 = 0.f, xr1 = 0.f;
                if (grow < NN) {
                    uint32_t w = g_xrbf[(size_t)grow * 64 + (col >> 1)];
                    xr0 = bf_lo(w); xr1 = bf_hi(w);
                }
                float v0 = fmaxf(acc[mt][nt][hrow * 2]     + xr0 + bias0, 0.f);
                float v1 = fmaxf(acc[mt][nt][hrow * 2 + 1] + xr1 + bias1, 0.f);
                *(uint32_t*)(smem + HOFF + rl * (BSTR * 2) + (col >> 1) * 4) = pack_bf16x2(v0, v1);
            }
        }
    }
    __syncthreads();

    // ---- W2 into B region ----
    for (int i = tid; i < 128 * 16; i += 256) {
        int n = i >> 4, c = i & 15;
        *(uint4*)(smem + BOFF + n * (BSTR * 2) + c * 16) = ((const uint4*)g_w2)[n * 16 + c];
    }
#pragma unroll
    for (int mt = 0; mt < 4; mt++)
#pragma unroll
        for (int nt = 0; nt < 4; nt++)
#pragma unroll
            for (int q = 0; q < 4; q++) acc[mt][nt][q] = 0.f;
    __syncthreads();

    // ---- mainloop 2: A = H ----
#pragma unroll
    for (int ks = 0; ks < 8; ks++) {
        const int k0 = ks * 16;
        uint32_t bf[4][2];
#pragma unroll
        for (int nt = 0; nt < 4; nt++) {
            int n = wc * 32 + nt * 8 + (lane >> 2);
            int bi = n * (BSTR / 2) + k0 / 2 + (lane & 3);
            bf[nt][0] = Bp[bi]; bf[nt][1] = Bp[bi + 4];
        }
#pragma unroll
        for (int mt = 0; mt < 4; mt++) {
            uint32_t ahp = smem_base + HOFF + (uint32_t)((wr * 64 + mt * 16) * BSTR + k0) * 2 + a_off;
            uint32_t ah[4];
            ldm_x4(ah, ahp);
#pragma unroll
            for (int nt = 0; nt < 4; nt++)
                mma_bf16(acc[mt][nt], ah, bf[nt][0], bf[nt][1]);
        }
    }

    // ---- epilogue 2: P bf16 / Q fp32 ----
#pragma unroll
    for (int nt = 0; nt < 4; nt++) {
        int col = wc * 32 + nt * 8 + (lane & 3) * 2;
        float bias0 = 0.f, bias1 = 0.f;
        if (col >= 64) {
            bias0 = __ldg(b2 + col - 64);
            bias1 = __ldg(b2 + col - 63);
        }
#pragma unroll
        for (int mt = 0; mt < 4; mt++) {
            int row0 = mbase + wr * 64 + mt * 16 + (lane >> 2);
#pragma unroll
            for (int hrow = 0; hrow < 2; hrow++) {
                int row = row0 + hrow * 8;
                if (row < NN) {
                    float v0 = acc[mt][nt][hrow * 2];
                    float v1 = acc[mt][nt][hrow * 2 + 1];
                    if (col < 64) {
                        g_pbf[(size_t)row * 32 + (col >> 1)] = pack_bf16x2(v0, v1);
                    } else {
                        *(float2*)(g_q + (size_t)row * 64 + (col - 64)) =
                            make_float2(v0 + bias0, v1 + bias1);
                    }
                }
            }
        }
    }
}

// ======================= final: log_softmax(mean_agg(P) + Q) =======================
__global__ void k_final(float* __restrict__ out) {
    int node = blockIdx.x * (blockDim.x >> 5) + (threadIdx.x >> 5);
    if (node >= NN) return;
    int lane = threadIdx.x & 31;
    int b = g_rowptr[node], e = g_rowptr[node + 1];
    float a0 = 0.f, a1 = 0.f;
    int i = b;
    for (; i + 4 <= e; i += 4) {
        int u0 = g_col[i + 0], u1 = g_col[i + 1], u2 = g_col[i + 2], u3 = g_col[i + 3];
        uint32_t w0 = g_pbf[(size_t)u0 * 32 + lane];
        uint32_t w1 = g_pbf[(size_t)u1 * 32 + lane];
        uint32_t w2 = g_pbf[(size_t)u2 * 32 + lane];
        uint32_t w3 = g_pbf[(size_t)u3 * 32 + lane];
        a0 += (bf_lo(w0) + bf_lo(w1)) + (bf_lo(w2) + bf_lo(w3));
        a1 += (bf_hi(w0) + bf_hi(w1)) + (bf_hi(w2) + bf_hi(w3));
    }
    for (; i < e; i++) {
        uint32_t w = g_pbf[(size_t)g_col[i] * 32 + lane];
        a0 += bf_lo(w);
        a1 += bf_hi(w);
    }
    float inv = 1.f / (float)max(e - b, 1);
    float2 q = *((const float2*)(g_q + (size_t)node * 64) + lane);
    float r0 = a0 * inv + q.x;
    float r1 = a1 * inv + q.y;

    float mx = fmaxf(r0, r1);
#pragma unroll
    for (int off = 16; off > 0; off >>= 1)
        mx = fmaxf(mx, __shfl_xor_sync(0xffffffffu, mx, off));
    float se = expf(r0 - mx) + expf(r1 - mx);
#pragma unroll
    for (int off = 16; off > 0; off >>= 1)
        se += __shfl_xor_sync(0xffffffffu, se, off);
    float l = logf(se);
    float2 o = make_float2(r0 - mx - l, r1 - mx - l);
    *((float2*)(out + (size_t)node * CC) + lane) = o;
}

// ======================= launch =======================
extern "C" void kernel_launch(void* const* d_in, const int* in_sizes, int n_in,
                              void* d_out, int out_size) {
    const float* x   = (const float*)d_in[0];
    const int*   ei  = (const int*)d_in[1];
    const int*   src = ei;
    const int*   dst = ei + NE;
    const float* W1l = (const float*)d_in[2];
    const float* b1l = (const float*)d_in[3];
    const float* W1r = (const float*)d_in[4];
    const float* W2l = (const float*)d_in[5];
    const float* b2l = (const float*)d_in[6];
    const float* W2r = (const float*)d_in[7];
    float* out = (float*)d_out;

    const int SMEM0  = 2 * 128 * BSTR * 2;   // 69632
    const int SMEM12 = 3 * 128 * BSTR * 2;   // 104448
    static cudaStream_t s2 = nullptr;
    static cudaEvent_t evF = nullptr, evX = nullptr, evJ = nullptr;
    if (!s2) {
        cudaStreamCreateWithFlags(&s2, cudaStreamNonBlocking);
        cudaEventCreateWithFlags(&evF, cudaEventDisableTiming);
        cudaEventCreateWithFlags(&evX, cudaEventDisableTiming);
        cudaEventCreateWithFlags(&evJ, cudaEventDisableTiming);
        cudaFuncSetAttribute(k_gemm0,  cudaFuncAttributeMaxDynamicSharedMemorySize, SMEM0);
        cudaFuncSetAttribute(k_gemm12, cudaFuncAttributeMaxDynamicSharedMemorySize, SMEM12);
    }

    const int NB = (NN + 127) / 128;

    // ---- fork: side stream: xconv -> prepW -> gemm0 ----
    cudaEventRecord(evF, 0);
    cudaStreamWaitEvent(s2, evF, 0);
    k_xconv<<<(NN * 64 + 255) / 256, 256, 0, s2>>>(x);
    cudaEventRecord(evX, s2);
    k_prepW<<<(128 * 256 + 128 * 128 + 255) / 256, 256, 0, s2>>>(W1l, W1r, W2l, W2r);
    k_gemm0<<<NB, 256, SMEM0, s2>>>();
    cudaEventRecord(evJ, s2);

    // ---- main chain: CSR build ----
    k_count<<<(NE + 255) / 256, 256>>>(dst);
    k_scan1<<<SCAN_NB, SCAN_B>>>();
    k_scan2<<<1, 128>>>();
    k_scan3<<<SCAN_NB, SCAN_B>>>();
    k_fill<<<(NE + 255) / 256, 256>>>(src, dst);

    // ---- aggregation (needs g_xbf), fused GEMM, final ----
    cudaStreamWaitEvent(0, evX, 0);
    k_agg128<<<(NN + 7) / 8, 256>>>();
    cudaStreamWaitEvent(0, evJ, 0);
    k_gemm12<<<NB, 256, SMEM12>>>(b1l, b2l);
    k_final<<<(NN + 7) / 8, 256>>>(out);
}